// round 15
// baseline (speedup 1.0000x reference)
#include <cuda_runtime.h>

#define NQ   12
#define DIM  4096
#define NL   5
#define NT   256
// pad-2 layout: loc(j) = j + 2*(j>>4) -> stride-18 rows, 16B-aligned rows
#define PAD_DIM (DIM + 2 * (DIM / 16))   // 4608 ull = 36 KB

typedef unsigned long long ull;
#define SGNMASK 0x8000000080000000ULL

__device__ __forceinline__ ull f32x2_mul(ull a, ull b) {
    ull r;
    asm("mul.rn.f32x2 %0, %1, %2;" : "=l"(r) : "l"(a), "l"(b));
    return r;
}
__device__ __forceinline__ ull f32x2_fma(ull a, ull b, ull c) {
    ull r;
    asm("fma.rn.f32x2 %0, %1, %2, %3;" : "=l"(r) : "l"(a), "l"(b), "l"(c));
    return r;
}
__device__ __forceinline__ ull swap_halves(ull v) {
    uint2 t = *reinterpret_cast<uint2*>(&v);
    uint2 s = make_uint2(t.y, t.x);
    return *reinterpret_cast<ull*>(&s);
}
__device__ __forceinline__ ull pack2(float lo, float hi) {
    uint2 t = make_uint2(__float_as_uint(lo), __float_as_uint(hi));
    return *reinterpret_cast<ull*>(&t);
}
__device__ __forceinline__ float2 cmul(float2 a, float2 b) {
    return make_float2(a.x * b.x - a.y * b.y, a.x * b.y + a.y * b.x);
}
__device__ __forceinline__ ulonglong2 packdup(float2 z) {
    return make_ulonglong2(pack2(z.x, z.x), pack2(-z.y, z.y));
}

// diagonal apply of a single per-thread constant (packed-dup form)
__device__ __forceinline__ void diag_const(ull a[16], const ulonglong2 e) {
    #pragma unroll
    for (int k = 0; k < 16; k++) {
        ull r = f32x2_mul(e.x, a[k]);
        a[k] = f32x2_fma(e.y, swap_halves(a[k]), r);
    }
}
// 4 real rotations: register-nibble bit m <-> qubit QBASE-m; coeffs {c,s} packed
template <int QBASE>
__device__ __forceinline__ void rots4(ull a[16], const ulonglong2* __restrict__ rotL) {
    #pragma unroll
    for (int m = 0; m < 4; m++) {
        const ulonglong2 cs = rotL[QBASE - m];
        const ull c  = cs.x;
        const ull s  = cs.y;
        const ull ns = s ^ SGNMASK;   // -s via sign-bit flip
        #pragma unroll
        for (int k = 0; k < 16; k++) {
            if (!(k & (1 << m))) {
                ull s0 = a[k], s1 = a[k | (1 << m)];
                ull n0 = f32x2_mul(c, s0);
                n0 = f32x2_fma(ns, s1, n0);
                ull n1 = f32x2_mul(s, s0);
                n1 = f32x2_fma(c,  s1, n1);
                a[k] = n0; a[k | (1 << m)] = n1;
            }
        }
    }
}

// fused gate angles -> full 2x2 complex matrix entries (U = RZ(b)RY(a)RX(g))
__device__ __forceinline__ void fuse_gate(float g, float aa, float bb,
                                          float2& u00, float2& u01,
                                          float2& u10, float2& u11) {
    float sg, cg, sa, ca, sb, cb;
    __sincosf(g,  &sg, &cg);
    __sincosf(aa, &sa, &ca);
    __sincosf(bb, &sb, &cb);
    float cc = ca * cg, ss = sa * sg, sc = sa * cg, cs = ca * sg;
    float2 e0 = make_float2(cb, -sb);
    float2 e1 = make_float2(cb,  sb);
    u00 = cmul(e0, make_float2(cc,   ss));
    u01 = cmul(e0, make_float2(-sc, -cs));
    u10 = cmul(e1, make_float2(sc,  -cs));
    u11 = cmul(e1, make_float2(cc,  -ss));
}

__global__ void __launch_bounds__(NT, 4)
qnet_kernel(const float* __restrict__ x,
            const float* __restrict__ iw,
            const float* __restrict__ th,
            const float* __restrict__ ow,
            float* __restrict__ out) {
    __shared__ __align__(16) ull st[PAD_DIM];       // 36 KB state
    __shared__ float2 d2Af[(NL - 1) * 16];  // D2_A entries (fold / layer-1 table)
    __shared__ float2 d1Cf[(NL - 1) * 16];  // D1_C entries (per-thread, next A)
    __shared__ float2 cAf[(NL - 1) * 16];   // D2_B entries (const in phase A)
    __shared__ float2 cB1f[(NL - 1) * 16];  // D1_A entries (const in phase B)
    __shared__ float2 cB2f[(NL - 1) * 16];  // D2_C entries (const in phase B)
    __shared__ float2 cCf[(NL - 1) * 16];   // D1_B entries (const in phase C)
    __shared__ __align__(16) ulonglong2 rot[(NL - 1) * NQ];   // {c,s} packed
    __shared__ float2 Za[(NL - 1) * NQ], Zb[(NL - 1) * NQ];   // e^{ip}, e^{iq}
    __shared__ float2 U00s[NQ], U10s[NQ];                     // layer-0 col-0
    __shared__ float red0[NT / 32], red1[NT / 32];

    const int b   = blockIdx.x;
    const int tid = threadIdx.x;

    // ---- stage 1: per-gate build + SU(2) Euler decomposition (60 threads) ----
    if (tid < NL * NQ) {
        const int l = tid / NQ, q = tid % NQ;
        float xin = tanhf(x[b * NQ + q]);
        float g  = 0.5f * iw[l * NQ + q] * xin;
        float aa = 0.5f * th[(l * NQ + q) * 2 + 0];
        float bb = 0.5f * th[(l * NQ + q) * 2 + 1];
        float2 u00, u01, u10, u11;
        fuse_gate(g, aa, bb, u00, u01, u10, u11);
        if (l == 0) {
            U00s[q] = u00;
            U10s[q] = u10;
        } else {
            float tc = sqrtf(u00.x * u00.x + u00.y * u00.y);
            float ts = sqrtf(u10.x * u10.x + u10.y * u10.y);
            float A_ = -atan2f(u00.y, u00.x);
            float B_ =  atan2f(u10.y, u10.x);
            float p  = 0.5f * (A_ + B_);
            float q2 = 0.5f * (A_ - B_);
            const int gi = (l - 1) * NQ + q;
            rot[gi] = make_ulonglong2(pack2(tc, tc), pack2(ts, ts));
            float sp, cp, sq, cq;
            __sincosf(p,  &sp, &cp);
            __sincosf(q2, &sq, &cq);
            Za[gi] = make_float2(cp, sp);   // bit=1 entry; bit=0 is conj
            Zb[gi] = make_float2(cq, sq);
        }
    }

    // ---- CNOT-ring maps (GF(2)-linear closed forms) ----
    int gt = tid ^ (tid >> 1); gt ^= gt >> 2; gt ^= gt >> 4;   // invgray(tid)
    const int par_t = gt & 1;
    const int F_t   = gt ^ (par_t << 11);
    const int DSTK[16] = {0x000, 0x9FF, 0xBFF, 0x200, 0xFFF, 0x600, 0x400, 0xDFF,
                          0x7FF, 0xE00, 0xC00, 0x5FF, 0x800, 0x1FF, 0x3FF, 0xA00};
    const bool S01K[16] = {0,1,1,0, 0,1,1,0, 1,0,0,1, 1,0,0,1};
    const bool S23K[16] = {0,1,0,1, 0,1,0,1, 0,1,0,1, 0,1,0,1};
    const bool PARK[16] = {0,1,1,0, 1,0,0,1, 1,0,0,1, 0,1,1,0};  // parity(k)
    // bits[11:8] of src_t (gather form) for the D1_C forward-deferral
    const int n0 = ((tid ^ (tid >> 1)) >> 4) & 15;

    const int bB = 18 * (tid & 0xF0) + (tid & 15);   // phase B: k at bB + 18k
    const int bC = tid + 2 * (tid >> 4);             // phase C: k at bC + 288k
    ulonglong2* st128 = reinterpret_cast<ulonglong2*>(st);

    ull a[16];
    __syncthreads();

    // ---- stage 2 (192 threads): kron diagonal products, routed to their ------
    // ---- application site; OVERLAPPED with layer-0 product-state compute ------
    if (tid < (NL - 1) * 3 * 16) {
        const int n  = tid & 15;
        const int lm = tid >> 4;            // 0..11
        const int lIdx = lm / 3, X = lm % 3;
        const int QB = 11 - 4 * X;          // QBASE of phase X
        float2 z2 = make_float2(1.f, 0.f), z1 = make_float2(1.f, 0.f);
        #pragma unroll
        for (int m = 0; m < 4; m++) {
            const int gi = lIdx * NQ + (QB - m);
            const int bit = (n >> m) & 1;
            float2 zb = Zb[gi]; if (!bit) zb.y = -zb.y;
            float2 za = Za[gi]; if (!bit) za.y = -za.y;
            z2 = cmul(z2, zb);
            z1 = cmul(z1, za);
        }
        if (X == 0) {        // D2_A -> fold in prev C (layer1: table in own A); D1_A -> const in B
            d2Af[lIdx * 16 + n] = z2;
            cB1f[lIdx * 16 + n] = z1;
        } else if (X == 1) { // D2_B -> const in A;  D1_B -> const in C
            cAf[lIdx * 16 + n] = z2;
            cCf[lIdx * 16 + n] = z1;
        } else {             // D2_C -> const in B;  D1_C -> per-thread in next A
            cB2f[lIdx * 16 + n] = z2;
            d1Cf[lIdx * 16 + n] = z1;
        }
    }

    // layer 0: |0..0> -> product state, scatter-stored (post-perm layout).
    // NOTE: reads nothing from stage 2 (race-free overlap).
    {
        float2 plow = make_float2(1.f, 0.f);
        #pragma unroll
        for (int p = 0; p < 8; p++) {                 // tid bit p <-> qubit 11-p
            float2 row = ((tid >> p) & 1) ? U10s[11 - p] : U00s[11 - p];
            plow = cmul(plow, row);
        }
        #pragma unroll
        for (int k = 0; k < 16; k++) {                // j = (k<<8) | tid
            float2 amp = plow;
            #pragma unroll
            for (int m = 0; m < 4; m++) {             // j bit 8+m <-> qubit 3-m
                float2 row = ((k >> m) & 1) ? U10s[3 - m] : U00s[3 - m];
                amp = cmul(amp, row);
            }
            int d = DSTK[k] ^ F_t;
            st[d + 2 * (d >> 4)] = pack2(amp.x, amp.y);
        }
    }
    __syncthreads();

    // ---------------- layers 1..4 ---------------------------------------------
    #pragma unroll 1
    for (int lIdx = 0; lIdx < NL - 1; lIdx++) {
        const ulonglong2* rotL = rot + lIdx * NQ;
        const bool last = (lIdx == NL - 2);

        // phase A
        #pragma unroll
        for (int q = 0; q < 8; q++) {
            ulonglong2 v = st128[9 * tid + q];
            a[2 * q] = v.x; a[2 * q + 1] = v.y;
        }
        if (lIdx == 0) {
            // layer 1's D2_A applied here as a 16-entry table (nibble = k)
            #pragma unroll
            for (int k = 0; k < 16; k++) {
                ulonglong2 e = packdup(d2Af[k]);
                ull r = f32x2_mul(e.x, a[k]);
                a[k] = f32x2_fma(e.y, swap_halves(a[k]), r);
            }
        } else {
            // deferred prev-layer D1_C (2 per-thread entries, k&1 select);
            // this layer's D2_A was folded backward in prev phase C
            const ulonglong2 E0 = packdup(d1Cf[(lIdx - 1) * 16 + n0]);
            const ulonglong2 E1 = packdup(d1Cf[(lIdx - 1) * 16 + (n0 ^ 12)]);
            #pragma unroll
            for (int k = 0; k < 16; k++) {
                ulonglong2 e = (k & 1) ? E1 : E0;
                ull r = f32x2_mul(e.x, a[k]);
                a[k] = f32x2_fma(e.y, swap_halves(a[k]), r);
            }
        }
        rots4<11>(a, rotL);
        diag_const(a, packdup(cAf[lIdx * 16 + (tid & 15)]));
        #pragma unroll
        for (int q = 0; q < 8; q++)
            st128[9 * tid + q] = make_ulonglong2(a[2 * q], a[2 * q + 1]);
        __syncwarp();

        // phase B: merged (D1_A * D2_C) const (last layer: D2_C only), rots(7..4)
        #pragma unroll
        for (int k = 0; k < 16; k++) a[k] = st[bB + 18 * k];
        {
            float2 zm = cB2f[lIdx * 16 + (tid >> 4)];
            if (!last) zm = cmul(zm, cB1f[lIdx * 16 + (tid & 15)]);
            diag_const(a, packdup(zm));
        }
        rots4<7>(a, rotL);
        #pragma unroll
        for (int k = 0; k < 16; k++) st[bB + 18 * k] = a[k];
        __syncthreads();

        // phase C: D1_B const (skip last), rots(3..0), next-layer D2_A fold,
        // CNOT-ring scatter (skip last)
        #pragma unroll
        for (int k = 0; k < 16; k++) a[k] = st[bC + 288 * k];
        if (!last) {
            diag_const(a, packdup(cCf[lIdx * 16 + (tid >> 4)]));
            rots4<3>(a, rotL);
            // backward-fold of layer (lIdx+2)'s... i.e. next lIdx's D2_A:
            // coefficient index = (gt&15) ^ (PARK[k] ? 0xF : 0) -> Z or conj(Z)
            const ulonglong2 EW = packdup(d2Af[(lIdx + 1) * 16 + (gt & 15)]);
            const ull EWdn = EW.y ^ SGNMASK;
            #pragma unroll
            for (int k = 0; k < 16; k++) {
                ull d = PARK[k] ? EWdn : EW.y;
                ull r = f32x2_mul(EW.x, a[k]);
                a[k] = f32x2_fma(d, swap_halves(a[k]), r);
            }
            #pragma unroll
            for (int k = 0; k < 16; k++) {
                int d = DSTK[k] ^ F_t;
                st[d + 2 * (d >> 4)] = a[k];
            }
            __syncthreads();
        } else {
            rots4<3>(a, rotL);     // no D1_B, no D1_C, no scatter (|amp|^2 next)
        }
    }

    // ---------------- measurement fused into last phase-C registers ------------
    float P0 = 0.f, P1 = 0.f, Q0 = 0.f, Q1 = 0.f;
    #pragma unroll
    for (int k = 0; k < 16; k++) {
        float2 v = *reinterpret_cast<float2*>(&a[k]);
        float pr = v.x * v.x + v.y * v.y;
        if (S01K[k]) P1 += pr; else P0 += pr;
        if (S23K[k]) Q1 += pr; else Q0 += pr;
    }
    float e01 = P0 - P1;
    if (par_t) e01 = -e01;
    float e23 = Q0 - Q1;

    #pragma unroll
    for (int off = 16; off > 0; off >>= 1) {
        e01 += __shfl_down_sync(0xffffffffu, e01, off);
        e23 += __shfl_down_sync(0xffffffffu, e23, off);
    }
    if ((tid & 31) == 0) { red0[tid >> 5] = e01; red1[tid >> 5] = e23; }
    __syncthreads();
    if (tid < 2) {
        const float* r = tid ? red1 : red0;
        float s = 0.f;
        #pragma unroll
        for (int w = 0; w < NT / 32; w++) s += r[w];
        out[b * 2 + tid] = ow[tid] * s;
    }
}

extern "C" void kernel_launch(void* const* d_in, const int* in_sizes, int n_in,
                              void* d_out, int out_size) {
    const float* x  = (const float*)d_in[0];   // (BATCH, 12)
    const float* iw = (const float*)d_in[1];   // (5, 12)
    const float* th = (const float*)d_in[2];   // (5, 12, 2)
    const float* ow = (const float*)d_in[3];   // (2,)
    float* out = (float*)d_out;                // (BATCH, 2)
    int batch = in_sizes[0] / NQ;
    qnet_kernel<<<batch, NT>>>(x, iw, th, ow, out);
}

// round 16
// speedup vs baseline: 1.0187x; 1.0187x over previous
#include <cuda_runtime.h>

#define NQ   12
#define DIM  4096
#define NL   5
#define NT   256
// pad-2 layout: loc(j) = j + 2*(j>>4) -> stride-18 rows, 16B-aligned rows
#define PAD_DIM (DIM + 2 * (DIM / 16))   // 4608 ull = 36 KB

typedef unsigned long long ull;

__device__ __forceinline__ ull f32x2_mul(ull a, ull b) {
    ull r;
    asm("mul.rn.f32x2 %0, %1, %2;" : "=l"(r) : "l"(a), "l"(b));
    return r;
}
__device__ __forceinline__ ull f32x2_fma(ull a, ull b, ull c) {
    ull r;
    asm("fma.rn.f32x2 %0, %1, %2, %3;" : "=l"(r) : "l"(a), "l"(b), "l"(c));
    return r;
}
__device__ __forceinline__ ull swap_halves(ull v) {
    uint2 t = *reinterpret_cast<uint2*>(&v);
    uint2 s = make_uint2(t.y, t.x);
    return *reinterpret_cast<ull*>(&s);
}
__device__ __forceinline__ ull pack2(float lo, float hi) {
    uint2 t = make_uint2(__float_as_uint(lo), __float_as_uint(hi));
    return *reinterpret_cast<ull*>(&t);
}
__device__ __forceinline__ float2 cmul(float2 a, float2 b) {
    return make_float2(a.x * b.x - a.y * b.y, a.x * b.y + a.y * b.x);
}
__device__ __forceinline__ ulonglong2 packdup(float2 z) {
    return make_ulonglong2(pack2(z.x, z.x), pack2(-z.y, z.y));
}

// diagonal apply from a 16-entry packed-dup table (indexed by register nibble)
__device__ __forceinline__ void diag_tab(ull a[16], const ulonglong2* __restrict__ t) {
    #pragma unroll
    for (int k = 0; k < 16; k++) {
        ulonglong2 e = t[k];
        ull r = f32x2_mul(e.x, a[k]);
        a[k] = f32x2_fma(e.y, swap_halves(a[k]), r);
    }
}
// diagonal apply of a single per-thread constant
__device__ __forceinline__ void diag_const(ull a[16], const ulonglong2 e) {
    #pragma unroll
    for (int k = 0; k < 16; k++) {
        ull r = f32x2_mul(e.x, a[k]);
        a[k] = f32x2_fma(e.y, swap_halves(a[k]), r);
    }
}
// 4 real rotations: register-nibble bit m <-> qubit QBASE-m; coeffs {c,s} packed
template <int QBASE>
__device__ __forceinline__ void rots4(ull a[16], const ulonglong2* __restrict__ rotL) {
    #pragma unroll
    for (int m = 0; m < 4; m++) {
        const ulonglong2 cs = rotL[QBASE - m];
        const ull c  = cs.x;
        const ull s  = cs.y;
        const ull ns = s ^ 0x8000000080000000ULL;   // -s via sign-bit flip
        #pragma unroll
        for (int k = 0; k < 16; k++) {
            if (!(k & (1 << m))) {
                ull s0 = a[k], s1 = a[k | (1 << m)];
                ull n0 = f32x2_mul(c, s0);
                n0 = f32x2_fma(ns, s1, n0);
                ull n1 = f32x2_mul(s, s0);
                n1 = f32x2_fma(c,  s1, n1);
                a[k] = n0; a[k | (1 << m)] = n1;
            }
        }
    }
}

// fused gate angles -> full 2x2 complex matrix entries (U = RZ(b)RY(a)RX(g))
__device__ __forceinline__ void fuse_gate(float g, float aa, float bb,
                                          float2& u00, float2& u01,
                                          float2& u10, float2& u11) {
    float sg, cg, sa, ca, sb, cb;
    __sincosf(g,  &sg, &cg);
    __sincosf(aa, &sa, &ca);
    __sincosf(bb, &sb, &cb);
    float cc = ca * cg, ss = sa * sg, sc = sa * cg, cs = ca * sg;
    float2 e0 = make_float2(cb, -sb);
    float2 e1 = make_float2(cb,  sb);
    u00 = cmul(e0, make_float2(cc,   ss));
    u01 = cmul(e0, make_float2(-sc, -cs));
    u10 = cmul(e1, make_float2(sc,  -cs));
    u11 = cmul(e1, make_float2(cc,  -ss));
}

__global__ void __launch_bounds__(NT, 4)
qnet_kernel(const float* __restrict__ x,
            const float* __restrict__ iw,
            const float* __restrict__ th,
            const float* __restrict__ ow,
            float* __restrict__ out) {
    __shared__ __align__(16) ull st[PAD_DIM];                    // 36 KB state
    __shared__ __align__(16) ulonglong2 d2Atab[(NL - 1) * 16];   // phase-A D2 tables
    __shared__ __align__(16) ulonglong2 d1Ctab[(NL - 1) * 16];   // phase-C D1 tables
    __shared__ float2 cAf[(NL - 1) * 16];    // D2_B entries  (const in phase A)
    __shared__ float2 cB1f[(NL - 1) * 16];   // D1_A entries  (const in phase B)
    __shared__ float2 cB2f[(NL - 1) * 16];   // D2_C entries  (const in phase B)
    __shared__ float2 cCf[(NL - 1) * 16];    // D1_B entries  (const in phase C)
    __shared__ __align__(16) ulonglong2 rot[(NL - 1) * NQ];      // {c,s} packed
    __shared__ float2 Za[(NL - 1) * NQ], Zb[(NL - 1) * NQ];      // e^{ip}, e^{iq}
    __shared__ float2 U00s[NQ], U10s[NQ];                        // layer-0 col-0
    __shared__ float red0[NT / 32], red1[NT / 32];

    const int b   = blockIdx.x;
    const int tid = threadIdx.x;

    // ---- stage 1: per-gate build + SU(2) Euler decomposition (60 threads) ----
    if (tid < NL * NQ) {
        const int l = tid / NQ, q = tid % NQ;
        float xin = tanhf(x[b * NQ + q]);
        float g  = 0.5f * iw[l * NQ + q] * xin;
        float aa = 0.5f * th[(l * NQ + q) * 2 + 0];
        float bb = 0.5f * th[(l * NQ + q) * 2 + 1];
        float2 u00, u01, u10, u11;
        fuse_gate(g, aa, bb, u00, u01, u10, u11);
        if (l == 0) {
            U00s[q] = u00;
            U10s[q] = u10;
        } else {
            float tc = sqrtf(u00.x * u00.x + u00.y * u00.y);
            float ts = sqrtf(u10.x * u10.x + u10.y * u10.y);
            float A_ = -atan2f(u00.y, u00.x);
            float B_ =  atan2f(u10.y, u10.x);
            float p  = 0.5f * (A_ + B_);
            float q2 = 0.5f * (A_ - B_);
            const int gi = (l - 1) * NQ + q;
            rot[gi] = make_ulonglong2(pack2(tc, tc), pack2(ts, ts));
            float sp, cp, sq, cq;
            __sincosf(p,  &sp, &cp);
            __sincosf(q2, &sq, &cq);
            Za[gi] = make_float2(cp, sp);   // bit=1 entry; bit=0 is conj
            Zb[gi] = make_float2(cq, sq);
        }
    }

    // ---- CNOT-ring scatter map (inverse perm), GF(2)-linear closed form ----
    int gt = tid ^ (tid >> 1); gt ^= gt >> 2; gt ^= gt >> 4;
    const int par_t = gt & 1;
    const int F_t   = gt ^ (par_t << 11);
    const int DSTK[16] = {0x000, 0x9FF, 0xBFF, 0x200, 0xFFF, 0x600, 0x400, 0xDFF,
                          0x7FF, 0xE00, 0xC00, 0x5FF, 0x800, 0x1FF, 0x3FF, 0xA00};
    const bool S01K[16] = {0,1,1,0, 0,1,1,0, 1,0,0,1, 1,0,0,1};
    const bool S23K[16] = {0,1,0,1, 0,1,0,1, 0,1,0,1, 0,1,0,1};

    const int bB = 18 * (tid & 0xF0) + (tid & 15);   // phase B: k at bB + 18k
    const int bC = tid + 2 * (tid >> 4);             // phase C: k at bC + 288k
    ulonglong2* st128 = reinterpret_cast<ulonglong2*>(st);

    ull a[16];
    __syncthreads();

    // ---- stage 2 (192 threads): kron diagonal products, routed to their ------
    // ---- application site; OVERLAPPED with layer-0 product-state compute ------
    if (tid < (NL - 1) * 3 * 16) {
        const int n  = tid & 15;
        const int lm = tid >> 4;            // 0..11
        const int lIdx = lm / 3, X = lm % 3;
        const int QB = 11 - 4 * X;          // QBASE of phase X
        float2 z2 = make_float2(1.f, 0.f), z1 = make_float2(1.f, 0.f);
        #pragma unroll
        for (int m = 0; m < 4; m++) {
            const int gi = lIdx * NQ + (QB - m);
            const int bit = (n >> m) & 1;
            float2 zb = Zb[gi]; if (!bit) zb.y = -zb.y;
            float2 za = Za[gi]; if (!bit) za.y = -za.y;
            z2 = cmul(z2, zb);
            z1 = cmul(z1, za);
        }
        if (X == 0) {        // phase A: D2 stays a table, D1 -> const in phase B
            d2Atab[lIdx * 16 + n] = packdup(z2);
            cB1f[lIdx * 16 + n]   = z1;
        } else if (X == 1) { // phase B: D2 -> const in phase A, D1 -> const in C
            cAf[lIdx * 16 + n] = z2;
            cCf[lIdx * 16 + n] = z1;
        } else {             // phase C: D2 -> const in phase B, D1 stays a table
            cB2f[lIdx * 16 + n]   = z2;
            d1Ctab[lIdx * 16 + n] = packdup(z1);
        }
    }

    // layer 0: |0..0> -> product state, scatter-stored (post-perm layout).
    // low-nibble factors built as a binary tree (36 cmuls instead of 72).
    {
        float2 plow = make_float2(1.f, 0.f);
        #pragma unroll
        for (int p = 0; p < 8; p++) {                 // tid bit p <-> qubit 11-p
            float2 row = ((tid >> p) & 1) ? U10s[11 - p] : U00s[11 - p];
            plow = cmul(plow, row);
        }
        // j bit 8+m <-> qubit 3-m:  m=0->q3, m=1->q2, m=2->q1, m=3->q0
        float2 w01[4], w23[4];
        #pragma unroll
        for (int i = 0; i < 4; i++) {                 // bits (m0,m1) = (i&1, i>>1)
            float2 f0 = (i & 1) ? U10s[3] : U00s[3];
            float2 f1 = (i & 2) ? U10s[2] : U00s[2];
            w01[i] = cmul(f0, f1);
        }
        #pragma unroll
        for (int i = 0; i < 4; i++) {                 // bits (m2,m3) = (i&1, i>>1)
            float2 f2 = (i & 1) ? U10s[1] : U00s[1];
            float2 f3 = (i & 2) ? U10s[0] : U00s[0];
            w23[i] = cmul(cmul(f2, f3), plow);        // fold plow in
        }
        #pragma unroll
        for (int k = 0; k < 16; k++) {                // j = (k<<8) | tid
            float2 amp = cmul(w01[k & 3], w23[k >> 2]);
            int d = DSTK[k] ^ F_t;
            st[d + 2 * (d >> 4)] = pack2(amp.x, amp.y);
        }
    }
    __syncthreads();

    // ---------------- layers 1..3 (full: D1s applied) --------------------------
    #pragma unroll 1
    for (int lIdx = 0; lIdx < NL - 2; lIdx++) {
        const ulonglong2* rotL = rot + lIdx * NQ;

        // phase A: D2_A table, rots(11..8), then D2_B as per-thread const
        #pragma unroll
        for (int q = 0; q < 8; q++) {
            ulonglong2 v = st128[9 * tid + q];
            a[2 * q] = v.x; a[2 * q + 1] = v.y;
        }
        diag_tab(a, d2Atab + lIdx * 16);
        rots4<11>(a, rotL);
        diag_const(a, packdup(cAf[lIdx * 16 + (tid & 15)]));
        #pragma unroll
        for (int q = 0; q < 8; q++)
            st128[9 * tid + q] = make_ulonglong2(a[2 * q], a[2 * q + 1]);
        __syncwarp();

        // phase B: merged (D1_A * D2_C) const, rots(7..4)
        #pragma unroll
        for (int k = 0; k < 16; k++) a[k] = st[bB + 18 * k];
        {
            float2 zm = cmul(cB1f[lIdx * 16 + (tid & 15)],
                             cB2f[lIdx * 16 + (tid >> 4)]);
            diag_const(a, packdup(zm));
        }
        rots4<7>(a, rotL);
        #pragma unroll
        for (int k = 0; k < 16; k++) st[bB + 18 * k] = a[k];
        __syncthreads();

        // phase C: D1_B const, rots(3..0), D1_C table, CNOT-ring scatter
        #pragma unroll
        for (int k = 0; k < 16; k++) a[k] = st[bC + 288 * k];
        diag_const(a, packdup(cCf[lIdx * 16 + (tid >> 4)]));
        rots4<3>(a, rotL);
        diag_tab(a, d1Ctab + lIdx * 16);
        #pragma unroll
        for (int k = 0; k < 16; k++) {
            int d = DSTK[k] ^ F_t;
            st[d + 2 * (d >> 4)] = a[k];
        }
        __syncthreads();
    }

    // ---------------- last layer: all D1 diagonals dropped (|amp|^2) -----------
    {
        const int lIdx = NL - 2;
        const ulonglong2* rotL = rot + lIdx * NQ;

        #pragma unroll
        for (int q = 0; q < 8; q++) {
            ulonglong2 v = st128[9 * tid + q];
            a[2 * q] = v.x; a[2 * q + 1] = v.y;
        }
        diag_tab(a, d2Atab + lIdx * 16);
        rots4<11>(a, rotL);
        diag_const(a, packdup(cAf[lIdx * 16 + (tid & 15)]));
        #pragma unroll
        for (int q = 0; q < 8; q++)
            st128[9 * tid + q] = make_ulonglong2(a[2 * q], a[2 * q + 1]);
        __syncwarp();

        #pragma unroll
        for (int k = 0; k < 16; k++) a[k] = st[bB + 18 * k];
        diag_const(a, packdup(cB2f[lIdx * 16 + (tid >> 4)]));   // D2_C only
        rots4<7>(a, rotL);
        #pragma unroll
        for (int k = 0; k < 16; k++) st[bB + 18 * k] = a[k];
        __syncthreads();

        #pragma unroll
        for (int k = 0; k < 16; k++) a[k] = st[bC + 288 * k];
        rots4<3>(a, rotL);          // no D1_B, no D1_C, no scatter
    }

    // ---------------- measurement fused into last phase-C registers ------------
    float P0 = 0.f, P1 = 0.f, Q0 = 0.f, Q1 = 0.f;
    #pragma unroll
    for (int k = 0; k < 16; k++) {
        float2 v = *reinterpret_cast<float2*>(&a[k]);
        float pr = v.x * v.x + v.y * v.y;
        if (S01K[k]) P1 += pr; else P0 += pr;
        if (S23K[k]) Q1 += pr; else Q0 += pr;
    }
    float e01 = P0 - P1;
    if (par_t) e01 = -e01;
    float e23 = Q0 - Q1;

    #pragma unroll
    for (int off = 16; off > 0; off >>= 1) {
        e01 += __shfl_down_sync(0xffffffffu, e01, off);
        e23 += __shfl_down_sync(0xffffffffu, e23, off);
    }
    if ((tid & 31) == 0) { red0[tid >> 5] = e01; red1[tid >> 5] = e23; }
    __syncthreads();
    if (tid < 2) {
        const float* r = tid ? red1 : red0;
        float s = 0.f;
        #pragma unroll
        for (int w = 0; w < NT / 32; w++) s += r[w];
        out[b * 2 + tid] = ow[tid] * s;
    }
}

extern "C" void kernel_launch(void* const* d_in, const int* in_sizes, int n_in,
                              void* d_out, int out_size) {
    const float* x  = (const float*)d_in[0];   // (BATCH, 12)
    const float* iw = (const float*)d_in[1];   // (5, 12)
    const float* th = (const float*)d_in[2];   // (5, 12, 2)
    const float* ow = (const float*)d_in[3];   // (2,)
    float* out = (float*)d_out;                // (BATCH, 2)
    int batch = in_sizes[0] / NQ;
    qnet_kernel<<<batch, NT>>>(x, iw, th, ow, out);
}

// round 17
// speedup vs baseline: 1.0196x; 1.0009x over previous
#include <cuda_runtime.h>

#define NQ   12
#define DIM  4096
#define NL   5
#define NT   256
// pad-2 layout: loc(j) = j + 2*(j>>4) -> stride-18 rows, 16B-aligned rows
#define PAD_DIM (DIM + 2 * (DIM / 16))   // 4608 ull = 36 KB

typedef unsigned long long ull;

__device__ __forceinline__ ull f32x2_mul(ull a, ull b) {
    ull r;
    asm("mul.rn.f32x2 %0, %1, %2;" : "=l"(r) : "l"(a), "l"(b));
    return r;
}
__device__ __forceinline__ ull f32x2_fma(ull a, ull b, ull c) {
    ull r;
    asm("fma.rn.f32x2 %0, %1, %2, %3;" : "=l"(r) : "l"(a), "l"(b), "l"(c));
    return r;
}
__device__ __forceinline__ ull swap_halves(ull v) {
    uint2 t = *reinterpret_cast<uint2*>(&v);
    uint2 s = make_uint2(t.y, t.x);
    return *reinterpret_cast<ull*>(&s);
}
__device__ __forceinline__ ull pack2(float lo, float hi) {
    uint2 t = make_uint2(__float_as_uint(lo), __float_as_uint(hi));
    return *reinterpret_cast<ull*>(&t);
}
__device__ __forceinline__ float2 cmul(float2 a, float2 b) {
    return make_float2(a.x * b.x - a.y * b.y, a.x * b.y + a.y * b.x);
}
__device__ __forceinline__ ulonglong2 packdup(float2 z) {
    return make_ulonglong2(pack2(z.x, z.x), pack2(-z.y, z.y));
}

// diagonal apply from a 16-entry packed-dup table (indexed by register nibble)
__device__ __forceinline__ void diag_tab(ull a[16], const ulonglong2* __restrict__ t) {
    #pragma unroll
    for (int k = 0; k < 16; k++) {
        ulonglong2 e = t[k];
        ull r = f32x2_mul(e.x, a[k]);
        a[k] = f32x2_fma(e.y, swap_halves(a[k]), r);
    }
}
// diagonal apply of a single per-thread constant
__device__ __forceinline__ void diag_const(ull a[16], const ulonglong2 e) {
    #pragma unroll
    for (int k = 0; k < 16; k++) {
        ull r = f32x2_mul(e.x, a[k]);
        a[k] = f32x2_fma(e.y, swap_halves(a[k]), r);
    }
}
// 4 real rotations: register-nibble bit m <-> qubit QBASE-m; coeffs {c,s} packed
template <int QBASE>
__device__ __forceinline__ void rots4(ull a[16], const ulonglong2* __restrict__ rotL) {
    #pragma unroll
    for (int m = 0; m < 4; m++) {
        const ulonglong2 cs = rotL[QBASE - m];
        const ull c  = cs.x;
        const ull s  = cs.y;
        const ull ns = s ^ 0x8000000080000000ULL;   // -s via sign-bit flip
        #pragma unroll
        for (int k = 0; k < 16; k++) {
            if (!(k & (1 << m))) {
                ull s0 = a[k], s1 = a[k | (1 << m)];
                ull n0 = f32x2_mul(c, s0);
                n0 = f32x2_fma(ns, s1, n0);
                ull n1 = f32x2_mul(s, s0);
                n1 = f32x2_fma(c,  s1, n1);
                a[k] = n0; a[k | (1 << m)] = n1;
            }
        }
    }
}

// fused gate angles -> full 2x2 complex matrix entries (U = RZ(b)RY(a)RX(g))
__device__ __forceinline__ void fuse_gate(float g, float aa, float bb,
                                          float2& u00, float2& u01,
                                          float2& u10, float2& u11) {
    float sg, cg, sa, ca, sb, cb;
    __sincosf(g,  &sg, &cg);
    __sincosf(aa, &sa, &ca);
    __sincosf(bb, &sb, &cb);
    float cc = ca * cg, ss = sa * sg, sc = sa * cg, cs = ca * sg;
    float2 e0 = make_float2(cb, -sb);
    float2 e1 = make_float2(cb,  sb);
    u00 = cmul(e0, make_float2(cc,   ss));
    u01 = cmul(e0, make_float2(-sc, -cs));
    u10 = cmul(e1, make_float2(sc,  -cs));
    u11 = cmul(e1, make_float2(cc,  -ss));
}

__global__ void __launch_bounds__(NT, 4)
qnet_kernel(const float* __restrict__ x,
            const float* __restrict__ iw,
            const float* __restrict__ th,
            const float* __restrict__ ow,
            float* __restrict__ out) {
    __shared__ __align__(16) ull st[PAD_DIM];                    // 36 KB state
    __shared__ __align__(16) ulonglong2 d2Atab[(NL - 1) * 16];   // phase-A D2 tables
    __shared__ __align__(16) ulonglong2 d1Ctab[(NL - 1) * 16];   // phase-C D1 tables
    __shared__ float2 cAf[(NL - 1) * 16];    // D2_B entries  (const in phase A)
    __shared__ float2 cB1f[(NL - 1) * 16];   // D1_A entries  (const in phase B)
    __shared__ float2 cB2f[(NL - 1) * 16];   // D2_C entries  (const in phase B)
    __shared__ float2 cCf[(NL - 1) * 16];    // D1_B entries  (const in phase C)
    __shared__ __align__(16) ulonglong2 rot[(NL - 1) * NQ];      // {c,s} packed
    __shared__ float2 Za[(NL - 1) * NQ], Zb[(NL - 1) * NQ];      // e^{ip}, e^{iq}
    __shared__ float2 U00s[NQ], U10s[NQ];                        // layer-0 col-0
    __shared__ float red0[NT / 32], red1[NT / 32];

    const int b   = blockIdx.x;
    const int tid = threadIdx.x;

    // ---- stage 1: per-gate build + SU(2) Euler decomposition (60 threads) ----
    if (tid < NL * NQ) {
        const int l = tid / NQ, q = tid % NQ;
        float xin = tanhf(x[b * NQ + q]);
        float g  = 0.5f * iw[l * NQ + q] * xin;
        float aa = 0.5f * th[(l * NQ + q) * 2 + 0];
        float bb = 0.5f * th[(l * NQ + q) * 2 + 1];
        float2 u00, u01, u10, u11;
        fuse_gate(g, aa, bb, u00, u01, u10, u11);
        if (l == 0) {
            U00s[q] = u00;
            U10s[q] = u10;
        } else {
            float tc = sqrtf(u00.x * u00.x + u00.y * u00.y);
            float ts = sqrtf(u10.x * u10.x + u10.y * u10.y);
            float A_ = -atan2f(u00.y, u00.x);
            float B_ =  atan2f(u10.y, u10.x);
            float p  = 0.5f * (A_ + B_);
            float q2 = 0.5f * (A_ - B_);
            const int gi = (l - 1) * NQ + q;
            rot[gi] = make_ulonglong2(pack2(tc, tc), pack2(ts, ts));
            float sp, cp, sq, cq;
            __sincosf(p,  &sp, &cp);
            __sincosf(q2, &sq, &cq);
            Za[gi] = make_float2(cp, sp);   // bit=1 entry; bit=0 is conj
            Zb[gi] = make_float2(cq, sq);
        }
    }

    // ---- CNOT-ring scatter map (inverse perm), GF(2)-linear closed form ----
    int gt = tid ^ (tid >> 1); gt ^= gt >> 2; gt ^= gt >> 4;
    const int par_t = gt & 1;
    const int F_t   = gt ^ (par_t << 11);
    const int DSTK[16] = {0x000, 0x9FF, 0xBFF, 0x200, 0xFFF, 0x600, 0x400, 0xDFF,
                          0x7FF, 0xE00, 0xC00, 0x5FF, 0x800, 0x1FF, 0x3FF, 0xA00};
    const bool S01K[16] = {0,1,1,0, 0,1,1,0, 1,0,0,1, 1,0,0,1};
    const bool S23K[16] = {0,1,0,1, 0,1,0,1, 0,1,0,1, 0,1,0,1};

    const int bB = 18 * (tid & 0xF0) + (tid & 15);   // phase B: k at bB + 18k
    const int bC = tid + 2 * (tid >> 4);             // phase C: k at bC + 288k
    ulonglong2* st128 = reinterpret_cast<ulonglong2*>(st);

    ull a[16];
    __syncthreads();

    // ---- stage 2 (192 threads): kron diagonal products, routed to their ------
    // ---- application site; OVERLAPPED with layer-0 product-state compute ------
    if (tid < (NL - 1) * 3 * 16) {
        const int n  = tid & 15;
        const int lm = tid >> 4;            // 0..11
        const int lIdx = lm / 3, X = lm % 3;
        const int QB = 11 - 4 * X;          // QBASE of phase X
        float2 z2 = make_float2(1.f, 0.f), z1 = make_float2(1.f, 0.f);
        #pragma unroll
        for (int m = 0; m < 4; m++) {
            const int gi = lIdx * NQ + (QB - m);
            const int bit = (n >> m) & 1;
            float2 zb = Zb[gi]; if (!bit) zb.y = -zb.y;
            float2 za = Za[gi]; if (!bit) za.y = -za.y;
            z2 = cmul(z2, zb);
            z1 = cmul(z1, za);
        }
        if (X == 0) {        // phase A: D2 stays a table, D1 -> const in phase B
            d2Atab[lIdx * 16 + n] = packdup(z2);
            cB1f[lIdx * 16 + n]   = z1;
        } else if (X == 1) { // phase B: D2 -> const in phase A, D1 -> const in C
            cAf[lIdx * 16 + n] = z2;
            cCf[lIdx * 16 + n] = z1;
        } else {             // phase C: D2 -> const in phase B, D1 stays a table
            cB2f[lIdx * 16 + n]   = z2;
            d1Ctab[lIdx * 16 + n] = packdup(z1);
        }
    }

    // layer 0: |0..0> -> product state, scatter-stored (post-perm layout).
    // low-nibble factors built as a binary tree (36 cmuls instead of 72).
    {
        float2 plow = make_float2(1.f, 0.f);
        #pragma unroll
        for (int p = 0; p < 8; p++) {                 // tid bit p <-> qubit 11-p
            float2 row = ((tid >> p) & 1) ? U10s[11 - p] : U00s[11 - p];
            plow = cmul(plow, row);
        }
        float2 w01[4], w23[4];
        #pragma unroll
        for (int i = 0; i < 4; i++) {
            float2 f0 = (i & 1) ? U10s[3] : U00s[3];
            float2 f1 = (i & 2) ? U10s[2] : U00s[2];
            w01[i] = cmul(f0, f1);
        }
        #pragma unroll
        for (int i = 0; i < 4; i++) {
            float2 f2 = (i & 1) ? U10s[1] : U00s[1];
            float2 f3 = (i & 2) ? U10s[0] : U00s[0];
            w23[i] = cmul(cmul(f2, f3), plow);        // fold plow in
        }
        #pragma unroll
        for (int k = 0; k < 16; k++) {                // j = (k<<8) | tid
            float2 amp = cmul(w01[k & 3], w23[k >> 2]);
            int d = DSTK[k] ^ F_t;
            st[d + 2 * (d >> 4)] = pack2(amp.x, amp.y);
        }
    }
    __syncthreads();

    // ---------------- layers 1..3 (full: D1s applied) --------------------------
    #pragma unroll 1
    for (int lIdx = 0; lIdx < NL - 2; lIdx++) {
        const ulonglong2* rotL = rot + lIdx * NQ;

        // phase A: const read FIRST (latency overlaps state loads), then
        // D2_A table, rots(11..8), D2_B const
        {
            const ulonglong2 eA = packdup(cAf[lIdx * 16 + (tid & 15)]);
            #pragma unroll
            for (int q = 0; q < 8; q++) {
                ulonglong2 v = st128[9 * tid + q];
                a[2 * q] = v.x; a[2 * q + 1] = v.y;
            }
            diag_tab(a, d2Atab + lIdx * 16);
            rots4<11>(a, rotL);
            diag_const(a, eA);
        }
        #pragma unroll
        for (int q = 0; q < 8; q++)
            st128[9 * tid + q] = make_ulonglong2(a[2 * q], a[2 * q + 1]);
        __syncwarp();

        // phase B: merged (D1_A * D2_C) const computed BEFORE state loads
        {
            float2 zm = cmul(cB1f[lIdx * 16 + (tid & 15)],
                             cB2f[lIdx * 16 + (tid >> 4)]);
            const ulonglong2 eB = packdup(zm);
            #pragma unroll
            for (int k = 0; k < 16; k++) a[k] = st[bB + 18 * k];
            diag_const(a, eB);
            rots4<7>(a, rotL);
        }
        #pragma unroll
        for (int k = 0; k < 16; k++) st[bB + 18 * k] = a[k];
        __syncthreads();

        // phase C: const FIRST, then D1_B const, rots(3..0), D1_C table, scatter
        {
            const ulonglong2 eC = packdup(cCf[lIdx * 16 + (tid >> 4)]);
            #pragma unroll
            for (int k = 0; k < 16; k++) a[k] = st[bC + 288 * k];
            diag_const(a, eC);
            rots4<3>(a, rotL);
            diag_tab(a, d1Ctab + lIdx * 16);
        }
        #pragma unroll
        for (int k = 0; k < 16; k++) {
            int d = DSTK[k] ^ F_t;
            st[d + 2 * (d >> 4)] = a[k];
        }
        __syncthreads();
    }

    // ---------------- last layer: all D1 diagonals dropped (|amp|^2) -----------
    {
        const int lIdx = NL - 2;
        const ulonglong2* rotL = rot + lIdx * NQ;

        {
            const ulonglong2 eA = packdup(cAf[lIdx * 16 + (tid & 15)]);
            #pragma unroll
            for (int q = 0; q < 8; q++) {
                ulonglong2 v = st128[9 * tid + q];
                a[2 * q] = v.x; a[2 * q + 1] = v.y;
            }
            diag_tab(a, d2Atab + lIdx * 16);
            rots4<11>(a, rotL);
            diag_const(a, eA);
        }
        #pragma unroll
        for (int q = 0; q < 8; q++)
            st128[9 * tid + q] = make_ulonglong2(a[2 * q], a[2 * q + 1]);
        __syncwarp();

        {
            const ulonglong2 eB = packdup(cB2f[lIdx * 16 + (tid >> 4)]); // D2_C only
            #pragma unroll
            for (int k = 0; k < 16; k++) a[k] = st[bB + 18 * k];
            diag_const(a, eB);
            rots4<7>(a, rotL);
        }
        #pragma unroll
        for (int k = 0; k < 16; k++) st[bB + 18 * k] = a[k];
        __syncthreads();

        #pragma unroll
        for (int k = 0; k < 16; k++) a[k] = st[bC + 288 * k];
        rots4<3>(a, rotL);          // no D1_B, no D1_C, no scatter
    }

    // ---------------- measurement fused into last phase-C registers ------------
    float P0 = 0.f, P1 = 0.f, Q0 = 0.f, Q1 = 0.f;
    #pragma unroll
    for (int k = 0; k < 16; k++) {
        float2 v = *reinterpret_cast<float2*>(&a[k]);
        float pr = v.x * v.x + v.y * v.y;
        if (S01K[k]) P1 += pr; else P0 += pr;
        if (S23K[k]) Q1 += pr; else Q0 += pr;
    }
    float e01 = P0 - P1;
    if (par_t) e01 = -e01;
    float e23 = Q0 - Q1;

    #pragma unroll
    for (int off = 16; off > 0; off >>= 1) {
        e01 += __shfl_down_sync(0xffffffffu, e01, off);
        e23 += __shfl_down_sync(0xffffffffu, e23, off);
    }
    if ((tid & 31) == 0) { red0[tid >> 5] = e01; red1[tid >> 5] = e23; }
    __syncthreads();
    if (tid < 2) {
        const float* r = tid ? red1 : red0;
        float s = 0.f;
        #pragma unroll
        for (int w = 0; w < NT / 32; w++) s += r[w];
        out[b * 2 + tid] = ow[tid] * s;
    }
}

extern "C" void kernel_launch(void* const* d_in, const int* in_sizes, int n_in,
                              void* d_out, int out_size) {
    const float* x  = (const float*)d_in[0];   // (BATCH, 12)
    const float* iw = (const float*)d_in[1];   // (5, 12)
    const float* th = (const float*)d_in[2];   // (5, 12, 2)
    const float* ow = (const float*)d_in[3];   // (2,)
    float* out = (float*)d_out;                // (BATCH, 2)
    int batch = in_sizes[0] / NQ;
    qnet_kernel<<<batch, NT>>>(x, iw, th, ow, out);
}